// round 13
// baseline (speedup 1.0000x reference)
#include <cuda_runtime.h>
#include <cuda_bf16.h>
#include <cstdint>

// Problem constants (fixed by reference: N=8192, D=256, K=8)
#define NC 1024      // number of classes
#define DD 256       // feature dim
#define KPC 8        // samples per class
#define NTOT (NC*KPC)
#define NBLK 272     // grid: 136 unique tiles x 2 column-halves
#define NCLS 256     // blocks that do phase-1 class work

__device__ __forceinline__ uint32_t smem_to_u32(const void* smem_ptr) {
    uint32_t addr;
    asm("{ .reg .u64 tmp; cvta.to.shared.u64 tmp, %1; cvt.u32.u64 %0, tmp; }"
        : "=r"(addr) : "l"(smem_ptr));
    return addr;
}

// ---------------------------------------------------------------------------
// Scratch (device globals; no allocation allowed)
// ---------------------------------------------------------------------------
__device__ __nv_bfloat16 g_centers_bf[NC * DD];  // bf16 class centers (MMA input)
__device__ float  g_sq[NC];                      // ||center||^2 per class (fp32)
__device__ float  g_distpc[NC];                  // sum of 8 dist_pc values per class
__device__ float  g_blocksum[NBLK];              // per-block (weighted) hinge totals
__device__ unsigned int g_c1 = 0;                // grid barrier counter
__device__ unsigned int g_c2 = 0;                // completion counter

// ---------------------------------------------------------------------------
// SMEM layout. Phase 1 stages 32KB of raw x into the A region.
// Phase 2: A = 64 rows, B = 32 rows (column-half), padded rows.
// ---------------------------------------------------------------------------
#define ROWB 528                     // padded row stride in bytes (264 bf16)
#define SMEM_SQR 0                   // 64 floats (row sq)
#define SMEM_SQC 256                 // 32 floats (col sq, this half)
#define SMEM_A   1024                // 64 rows * 528 B = 33792 (phase1: 32KB x)
#define SMEM_B   (1024 + 33792)      // 32 rows * 528 B = 16896
#define GRAM_SMEM (SMEM_B + 16896)   // 51712 B dynamic

#define CP_ASYNC_16(dst, src) \
    asm volatile("cp.async.cg.shared.global [%0], [%1], 16;" :: "r"(dst), "l"(src))
#define CP_COMMIT() asm volatile("cp.async.commit_group;" ::: "memory")
#define CP_WAIT(n)  asm volatile("cp.async.wait_group %0;" :: "n"(n) : "memory")

__device__ __forceinline__ void ldsm_x4(uint32_t* r, uint32_t addr) {
    asm volatile("ldmatrix.sync.aligned.m8n8.x4.shared.b16 {%0,%1,%2,%3}, [%4];"
        : "=r"(r[0]), "=r"(r[1]), "=r"(r[2]), "=r"(r[3]) : "r"(addr));
}
__device__ __forceinline__ void mma_bf16(float* c, const uint32_t* a, const uint32_t* b) {
    asm volatile(
        "mma.sync.aligned.m16n8k16.row.col.f32.bf16.bf16.f32 "
        "{%0,%1,%2,%3}, {%4,%5,%6,%7}, {%8,%9}, {%0,%1,%2,%3};"
        : "+f"(c[0]), "+f"(c[1]), "+f"(c[2]), "+f"(c[3])
        : "r"(a[0]), "r"(a[1]), "r"(a[2]), "r"(a[3]), "r"(b[0]), "r"(b[1]));
}
__device__ __forceinline__ float4 lds128f(uint32_t a) {
    float4 r;
    asm volatile("ld.shared.v4.f32 {%0,%1,%2,%3}, [%4];"
        : "=f"(r.x), "=f"(r.y), "=f"(r.z), "=f"(r.w) : "r"(a));
    return r;
}

// ---------------------------------------------------------------------------
// Single fused kernel, 272 blocks x 256 threads, 2 blocks/SM (272 <= 296
// resident slots -> spin barrier deadlock-free).
// Phase 1 (blocks 0..255): centers/sq/distpc. Barrier. Phase 2 (all 272):
// one 64x32 half of an upper-triangle gram tile (off-diag weighted x2).
// ---------------------------------------------------------------------------
__global__ void __launch_bounds__(256, 2) fused_kernel(const float* __restrict__ x,
                                                       float* __restrict__ out,
                                                       int n_out)
{
    extern __shared__ char smem[];
    const uint32_t sbase = smem_to_u32(smem);
    const int tid  = threadIdx.x;
    const int warp = tid >> 5;
    const int lane = tid & 31;
    const int bid  = blockIdx.x;

    __shared__ float rn[4][2][KPC];          // phase-1 partial row sumsq
    __shared__ float cpp[4][2];              // phase-1 partial center sumsq
    __shared__ float dp[4][2][KPC];          // phase-1 partial center dots
    __shared__ float wsum[8];
    __shared__ float sa[8], sp[8];
    __shared__ unsigned int s_last;

    // ====================== Phase 1 (blocks 0..255) ========================
    if (bid < NCLS) {
        const int ci   = warp >> 1;          // class within block (0..3)
        const int half = warp & 1;           // dim half (0..1)
        const int c    = bid * 4 + ci;

        {   // stage block's 32 rows (32KB) via cp.async
            const char* xsrc = (const char*)(x + (size_t)bid * 4 * KPC * DD);
#pragma unroll
            for (int it = 0; it < 8; it++) {
                int ch = tid + it * 256;                 // 0..2047 chunks of 16B
                CP_ASYNC_16(sbase + SMEM_A + ch * 16, xsrc + ch * 16);
            }
            CP_COMMIT();
            CP_WAIT(0);
            __syncthreads();
        }

        const uint32_t xoff = sbase + SMEM_A + ci * (KPC * 1024) + half * 512 + lane * 16;

        float s[KPC];
#pragma unroll
        for (int r = 0; r < KPC; r++) {
            float4 q = lds128f(xoff + r * 1024);
            s[r] = q.x * q.x + q.y * q.y + q.z * q.z + q.w * q.w;
        }
#pragma unroll
        for (int off = 16; off; off >>= 1)
#pragma unroll
            for (int r = 0; r < KPC; r++)
                s[r] += __shfl_xor_sync(0xffffffffu, s[r], off);
        if (lane == 0) {
#pragma unroll
            for (int r = 0; r < KPC; r++) rn[ci][half][r] = s[r];
        }
        __syncthreads();

        float inv[KPC];
        float ctr[4] = {0.f, 0.f, 0.f, 0.f};
#pragma unroll
        for (int r = 0; r < KPC; r++) {
            inv[r] = rsqrtf(rn[ci][0][r] + rn[ci][1][r]);
            float4 q = lds128f(xoff + r * 1024);
            ctr[0] += q.x * inv[r]; ctr[1] += q.y * inv[r];
            ctr[2] += q.z * inv[r]; ctr[3] += q.w * inv[r];
        }
#pragma unroll
        for (int j = 0; j < 4; j++) ctr[j] *= (1.0f / KPC);

        {   // bf16 center store (8B per lane, coalesced)
            __nv_bfloat162 p0 = __floats2bfloat162_rn(ctr[0], ctr[1]);
            __nv_bfloat162 p1 = __floats2bfloat162_rn(ctr[2], ctr[3]);
            uint2 u;
            u.x = *(uint32_t*)&p0; u.y = *(uint32_t*)&p1;
            *(uint2*)(&g_centers_bf[c * DD + half * 128 + lane * 4]) = u;
        }

        float cs = ctr[0]*ctr[0] + ctr[1]*ctr[1] + ctr[2]*ctr[2] + ctr[3]*ctr[3];
#pragma unroll
        for (int off = 16; off; off >>= 1)
            cs += __shfl_xor_sync(0xffffffffu, cs, off);
        if (lane == 0) cpp[ci][half] = cs;
        __syncthreads();
        const float csf = cpp[ci][0] + cpp[ci][1];

        // early barrier arrival
        if (tid == 0) {
#pragma unroll
            for (int k = 0; k < 4; k++) g_sq[bid * 4 + k] = cpp[k][0] + cpp[k][1];
            __threadfence();
            atomicAdd(&g_c1, 1u);
        }

        // dist_pc overlaps barrier wait: ||xn-cn||^2 = 2 - 2*bc*dot(xn,ctr)
        {
            float dt[KPC];
#pragma unroll
            for (int r = 0; r < KPC; r++) {
                float4 q = lds128f(xoff + r * 1024);
                dt[r] = (q.x*ctr[0] + q.y*ctr[1] + q.z*ctr[2] + q.w*ctr[3]) * inv[r];
            }
#pragma unroll
            for (int off = 16; off; off >>= 1)
#pragma unroll
                for (int r = 0; r < KPC; r++)
                    dt[r] += __shfl_xor_sync(0xffffffffu, dt[r], off);
            if (lane == 0) {
#pragma unroll
                for (int r = 0; r < KPC; r++) dp[ci][half][r] = dt[r];
            }
            __syncthreads();
            if (half == 0 && lane == 0) {
                const float bc = rsqrtf(csf);
                float acc = 0.f;
#pragma unroll
                for (int r = 0; r < KPC; r++) {
                    float dd2 = 2.0f - 2.0f * bc * (dp[ci][0][r] + dp[ci][1][r]);
                    acc += sqrtf(fmaxf(dd2, 0.0f));          // MARGIN1 = 0
                }
                g_distpc[c] = acc;
            }
        }
    } else {
        // no class work: arrive immediately
        if (tid == 0) atomicAdd(&g_c1, 1u);
    }

    // ====================== Barrier spin (acquire) =========================
    if (tid == 0) {
        unsigned int vv;
        do {
            asm volatile("ld.global.acquire.gpu.u32 %0, [%1];"
                         : "=r"(vv) : "l"(&g_c1));
        } while (vv < (unsigned)NBLK);
    }
    __syncthreads();

    // ====================== Phase 2: 64x32 half-tile =======================
    {
        // decode job: tile t = bid>>1 (upper triangle, i<=j), column half hN
        const int t  = bid >> 1;
        const int hN = bid & 1;
        int ti = 0, tt = t;
        while (tt >= 16 - ti) { tt -= 16 - ti; ti++; }
        const int tj = ti + tt;
        const int rb = ti * 64;
        const int cb = tj * 64 + hN * 32;          // this half's 32 columns
        const float wgt = (ti == tj) ? 1.0f : 2.0f;

        // stage A (64 rows) + B (32 rows): 96 rows x 32 chunks = 3072 chunks.
        // Each commit group stages ALL 96 rows' K-half s2 (16 chunks/row):
        // 96*16 = 1536 chunks = 6 iterations of 256 threads.
#pragma unroll
        for (int s2 = 0; s2 < 2; s2++) {
#pragma unroll
            for (int it = 0; it < 6; it++) {
                int ch  = tid + it * 256;              // 0..1535
                int row = ch >> 4;                     // 0..95
                int cq  = (ch & 15) + s2 * 16;         // chunk 0..31
                int gr  = (row < 64) ? (rb + row) : (cb + row - 64);
                uint32_t dst = sbase + ((row < 64) ? SMEM_A + row * ROWB
                                                   : SMEM_B + (row - 64) * ROWB) + cq * 16;
                CP_ASYNC_16(dst, (const char*)&g_centers_bf[gr * DD + cq * 8]);
            }
            CP_COMMIT();
        }

        if (tid < 64)       ((float*)(smem + SMEM_SQR))[tid]      = __ldcg(&g_sq[rb + tid]);
        else if (tid < 96)  ((float*)(smem + SMEM_SQC))[tid - 64] = __ldcg(&g_sq[cb + tid - 64]);

        // warp layout: 4 row strips of 16 x 2 col strips of 16
        const int wrow = warp & 3;
        const int wcol = warp >> 2;

        // split accumulators per K-half: 2 n8-slices of m16n8
        float acc[2][2][4];
#pragma unroll
        for (int h = 0; h < 2; h++)
#pragma unroll
            for (int ni = 0; ni < 2; ni++)
#pragma unroll
                for (int q = 0; q < 4; q++) acc[h][ni][q] = 0.f;

        const uint32_t aBase = sbase + SMEM_A + (wrow * 16 + (lane & 15)) * ROWB + (lane >> 4) * 16;
        const uint32_t bBase = sbase + SMEM_B
            + (wcol * 16 + (lane & 7) + ((lane >> 4) << 3)) * ROWB + ((lane >> 3) & 1) * 16;

        CP_WAIT(1);
        __syncthreads();

#pragma unroll
        for (int h = 0; h < 2; h++) {
            if (h == 1) { CP_WAIT(0); __syncthreads(); }
#pragma unroll
            for (int s0 = 0; s0 < 8; s0++) {
                const int koff = (h * 8 + s0) * 32;
                uint32_t a[4], b[4];
                ldsm_x4(a, aBase + koff);
                ldsm_x4(b, bBase + koff);
                mma_bf16(acc[h][0], a, &b[0]);
                mma_bf16(acc[h][1], a, &b[2]);
            }
        }

        // fused hinge epilogue -> one scalar per thread (8 terms)
        const float* sqR = (const float*)(smem + SMEM_SQR);
        const float* sqC = (const float*)(smem + SMEM_SQC);
        float hsum = 0.f;
        {
            const int lr0 = wrow * 16 + (lane >> 2);
            const int lr1 = lr0 + 8;
            const float sq0 = sqR[lr0], sq1 = sqR[lr1];
            const int r0 = rb + lr0, r1 = rb + lr1;
#pragma unroll
            for (int ni = 0; ni < 2; ni++) {
#pragma unroll
                for (int q = 0; q < 2; q++) {
                    const int lc  = wcol * 16 + ni * 8 + (lane & 3) * 2 + q;
                    const int col = cb + lc;
                    const float sqc = sqC[lc];
                    if (col != r0) {
                        float G   = acc[0][ni][q] + acc[1][ni][q];
                        float dsq = sq0 + sqc - 2.0f * G;
                        hsum += fmaxf(0.7f - sqrtf(fmaxf(dsq, 1e-12f)), 0.f);
                    }
                    if (col != r1) {
                        float G   = acc[0][ni][q + 2] + acc[1][ni][q + 2];
                        float dsq = sq1 + sqc - 2.0f * G;
                        hsum += fmaxf(0.7f - sqrtf(fmaxf(dsq, 1e-12f)), 0.f);
                    }
                }
            }
        }
#pragma unroll
        for (int off = 16; off; off >>= 1)
            hsum += __shfl_xor_sync(0xffffffffu, hsum, off);
        if (lane == 0) wsum[warp] = hsum;
        __syncthreads();
        if (tid == 0) {
            float bsum = 0.f;
#pragma unroll
            for (int w = 0; w < 8; w++) bsum += wsum[w];
            g_blocksum[bid] = bsum * wgt;
        }
    }

    // ====================== Tail: last block finalizes =====================
    if (tid == 0) {
        __threadfence();
        unsigned int old = atomicAdd(&g_c2, 1u);
        s_last = (old == (unsigned)(NBLK - 1));
    }
    __syncthreads();

    if (s_last) {
        float an = __ldcg(&g_blocksum[tid]);
        if (tid < NBLK - 256) an += __ldcg(&g_blocksum[tid + 256]);
        float pc = 0.f;
#pragma unroll
        for (int p = 0; p < 4; p++) pc += __ldcg(&g_distpc[tid + p * 256]);
#pragma unroll
        for (int off = 16; off; off >>= 1) {
            an += __shfl_xor_sync(0xffffffffu, an, off);
            pc += __shfl_xor_sync(0xffffffffu, pc, off);
        }
        if (lane == 0) { sa[warp] = an; sp[warp] = pc; }
        __syncthreads();
        if (tid == 0) {
            float An = 0.f, Pc = 0.f;
#pragma unroll
            for (int w = 0; w < 8; w++) { An += sa[w]; Pc += sp[w]; }
            float anm = An * (1.0f / (1023.0f * NC));
            float pcm = Pc * (1.0f / NTOT);
            if (n_out > 0) out[0] = pcm + anm;
            if (n_out > 1) out[1] = pcm;
            if (n_out > 2) out[2] = anm;
            g_c1 = 0;                 // self-reset for next graph replay
            g_c2 = 0;
        }
    }
}

extern "C" void kernel_launch(void* const* d_in, const int* in_sizes, int n_in,
                              void* d_out, int out_size)
{
    const float* x = (const float*)d_in[0];
    (void)in_sizes; (void)n_in;

    cudaFuncSetAttribute(fused_kernel,
                         cudaFuncAttributeMaxDynamicSharedMemorySize, GRAM_SMEM);

    fused_kernel<<<NBLK, 256, GRAM_SMEM>>>(x, (float*)d_out, out_size);
}